// round 15
// baseline (speedup 1.0000x reference)
#include <cuda_runtime.h>
#include <cstdint>

// YoloV1Loss: pred/label (16384, 30, 7, 7) fp32 -> scalar fp32.
// TMA bulk-copy ping-pong: 2-batch tiles (23.52KB stages, tile stride 11760B
// = 16B multiple so every global src stays aligned), 2 stages/block ->
// 4 blocks/SM (GRID=592). 8 interleaved copies per stage (R12's granularity).
// Deterministic two-level reduction (ticket/last-block, self-resetting).

#define BLOCK 128
static constexpr int BATCH   = 16384;
static constexpr int NCH     = 30;
static constexpr int NCOL    = 7;
static constexpr int SPAT    = 49;
static constexpr int CHSTR   = SPAT;
static constexpr int BSTR    = NCH * SPAT;            // 1470 floats/batch
static constexpr int NB      = 2;                     // batches per tile (even!)
static constexpr int TILE_F  = NB * BSTR;             // 2940 floats per tensor
static constexpr int TILE_B  = TILE_F * 4;            // 11760 bytes (16B mult.)
// 4 chunks per tensor, all 16B multiples: 2944*3 + 2928 = 11760.
static constexpr int CH0 = 0,     CSZ0 = 2944;
static constexpr int CH1 = 2944,  CSZ1 = 2944;
static constexpr int CH2 = 5888,  CSZ2 = 2944;
static constexpr int CH3 = 8832,  CSZ3 = 2928;
static constexpr int STAGE_F = 2 * TILE_F;            // 5880 floats (pred+label)
static constexpr int STAGE_B = 2 * TILE_B;            // 23520 bytes
static constexpr int NSTAGES = 2;                     // ping-pong
static constexpr int SMEM_DYN = NSTAGES * STAGE_B;    // 47040 bytes
static constexpr int NTILES  = BATCH / NB;            // 8192
static constexpr int GRID    = 592;                   // 4 blocks/SM x 148
static constexpr int CELLS   = NB * SPAT;             // 98

__device__ float        g_partials[GRID];
__device__ unsigned int g_count = 0;

__device__ __forceinline__ uint32_t smem_u32(const void* p) {
    uint32_t a;
    asm("{ .reg .u64 t; cvta.to.shared.u64 t, %1; cvt.u32.u64 %0, t; }"
        : "=r"(a) : "l"(p));
    return a;
}

__device__ __forceinline__ void mbar_init(uint32_t mbar, uint32_t count) {
    asm volatile("mbarrier.init.shared.b64 [%0], %1;" :: "r"(mbar), "r"(count) : "memory");
}

__device__ __forceinline__ void mbar_wait(uint32_t mbar, uint32_t parity) {
    asm volatile(
        "{\n\t.reg .pred P;\n\t"
        "WAIT_%=:\n\t"
        "mbarrier.try_wait.parity.acquire.cta.shared::cta.b64 P, [%0], %1, 0x989680;\n\t"
        "@P bra.uni DONE_%=;\n\t"
        "bra.uni WAIT_%=;\n\t"
        "DONE_%=:\n\t}"
        :: "r"(mbar), "r"(parity) : "memory");
}

__device__ __forceinline__ void bulk_cp(uint32_t dst, const void* src,
                                        uint32_t bytes, uint32_t mbar) {
    asm volatile("cp.async.bulk.shared::cluster.global.mbarrier::complete_tx::bytes "
                 "[%0], [%1], %2, [%3];"
                 :: "r"(dst), "l"(src), "r"(bytes), "r"(mbar) : "memory");
}

// Issue one tile: expect_tx + 8 interleaved bulk copies (pred/label x4 chunks).
__device__ __forceinline__ void issue_tile(uint32_t stage_smem, uint32_t mbar,
                                           const float* __restrict__ pred,
                                           const float* __restrict__ label,
                                           int tile) {
    const char* srcp = (const char*)pred  + (size_t)tile * TILE_B;
    const char* srcl = (const char*)label + (size_t)tile * TILE_B;
    const uint32_t dl = stage_smem + TILE_B;   // label half of stage
    asm volatile("mbarrier.arrive.expect_tx.shared::cta.b64 _, [%0], %1;"
                 :: "r"(mbar), "r"((uint32_t)STAGE_B) : "memory");
    bulk_cp(stage_smem + CH0, srcp + CH0, CSZ0, mbar);
    bulk_cp(dl         + CH0, srcl + CH0, CSZ0, mbar);
    bulk_cp(stage_smem + CH1, srcp + CH1, CSZ1, mbar);
    bulk_cp(dl         + CH1, srcl + CH1, CSZ1, mbar);
    bulk_cp(stage_smem + CH2, srcp + CH2, CSZ2, mbar);
    bulk_cp(dl         + CH2, srcl + CH2, CSZ2, mbar);
    bulk_cp(stage_smem + CH3, srcp + CH3, CSZ3, mbar);
    bulk_cp(dl         + CH3, srcl + CH3, CSZ3, mbar);
}

__device__ __forceinline__ float iou_calc(float ax1, float ay1, float ax2, float ay2,
                                          float bx1, float by1, float bx2, float by2) {
    float iw = fmaxf(fminf(ax2, bx2) - fmaxf(ax1, bx1), 0.0f);
    float ih = fmaxf(fminf(ay2, by2) - fmaxf(ay1, by1), 0.0f);
    float inter = iw * ih;
    float area_a = (ax2 - ax1) * (ay2 - ay1);
    float area_b = (bx2 - bx1) * (by2 - by1);
    return inter / (area_a + area_b - inter + 1e-10f);
}

// Full per-cell loss from smem tile. pp/ll point at channel-0 of this cell.
__device__ __forceinline__ float cell_loss(const float* __restrict__ pp,
                                           const float* __restrict__ ll,
                                           int row, int col) {
    float p[10], lb[9];
    #pragma unroll
    for (int c = 0; c < 10; c++) p[c]  = pp[c * CHSTR];
    #pragma unroll
    for (int c = 0; c < 9;  c++) lb[c] = ll[c * CHSTR];

    float cl0 = 0.0f, cl1 = 0.0f;
    #pragma unroll
    for (int c = 10; c < NCH; c += 2) {
        float d0 = pp[c * CHSTR]       - ll[c * CHSTR];
        float d1 = pp[(c + 1) * CHSTR] - ll[(c + 1) * CHSTR];
        cl0 = fmaf(d0, d0, cl0);
        cl1 = fmaf(d1, d1, cl1);
    }
    float class_l = cl0 + cl1;

    const float inv = 1.0f / (float)NCOL;
    float fc = (float)col, fr = (float)row;

    float cx = (p[0] + fc) * inv, cy = (p[1] + fr) * inv;
    float a1x1 = cx - 0.5f * p[2], a1y1 = cy - 0.5f * p[3];
    float a1x2 = cx + 0.5f * p[2], a1y2 = cy + 0.5f * p[3];
    cx = (p[5] + fc) * inv; cy = (p[6] + fr) * inv;
    float a2x1 = cx - 0.5f * p[7], a2y1 = cy - 0.5f * p[8];
    float a2x2 = cx + 0.5f * p[7], a2y2 = cy + 0.5f * p[8];
    cx = (lb[0] + fc) * inv; cy = (lb[1] + fr) * inv;
    float lx1 = cx - 0.5f * lb[2], ly1 = cy - 0.5f * lb[3];
    float lx2 = cx + 0.5f * lb[2], ly2 = cy + 0.5f * lb[3];

    float iou1 = iou_calc(a1x1, a1y1, a1x2, a1y2, lx1, ly1, lx2, ly2);
    float iou2 = iou_calc(a2x1, a2y1, a2x2, a2y2, lx1, ly1, lx2, ly2);
    bool choose1 = (iou1 >= iou2);

    float d0 = p[0] - lb[0], d1 = p[1] - lb[1];
    float sw1 = sqrtf(p[2]) - sqrtf(lb[2]);
    float sh1 = sqrtf(p[3]) - sqrtf(lb[3]);
    float coord1 = 5.0f * (d0 * d0 + d1 * d1) + sw1 * sw1 + sh1 * sh1;

    float e0 = p[5] - lb[5], e1 = p[6] - lb[6];
    float sw2 = sqrtf(p[7]) - sqrtf(lb[7]);
    float sh2 = sqrtf(p[8]) - sqrtf(lb[8]);
    float coord2 = 5.0f * (e0 * e0 + e1 * e1) + sw2 * sw2 + sh2 * sh2;

    float o1 = p[4] - iou1; float obj1 = o1 * o1;
    float o2 = p[9] - iou2; float obj2 = o2 * o2;

    float coord      = choose1 ? coord1 : coord2;
    float obj_conf   = choose1 ? obj1   : obj2;
    float noobj_conf = 0.5f * (choose1 ? obj2 : obj1);

    float obj_cell = coord + obj_conf + noobj_conf + class_l;
    float nsum = p[4] + p[9];
    float noobj_cell = 0.5f * nsum * nsum;

    return (lb[4] == 1.0f) ? obj_cell : noobj_cell;
}

__global__ void __launch_bounds__(BLOCK) yolo_loss_tma(
    const float* __restrict__ pred, const float* __restrict__ label,
    float* __restrict__ out) {
    extern __shared__ float smem[];
    __shared__ __align__(8) unsigned long long mbar_store[NSTAGES];

    const uint32_t smem_base = smem_u32(smem);
    const uint32_t mbar_base = smem_u32(mbar_store);
    const int tid = threadIdx.x;

    if (tid == 0) {
        #pragma unroll
        for (int s = 0; s < NSTAGES; s++) mbar_init(mbar_base + s * 8, 1);
    }
    __syncthreads();

    // Prologue: fill both stages.
    if (tid == 0) {
        #pragma unroll
        for (int j = 0; j < NSTAGES; j++) {
            int tile = blockIdx.x + j * GRID;
            if (tile < NTILES)
                issue_tile(smem_base + j * STAGE_B, mbar_base + j * 8, pred, label, tile);
        }
    }

    // Cell geometry (fixed across tiles). Threads 98..127 idle in compute.
    const bool active = (tid < CELLS);
    int bl = 0, s2 = 0, row = 0, col = 0;
    if (active) {
        bl = tid / SPAT;
        s2 = tid - bl * SPAT;
        row = s2 / NCOL;
        col = s2 - row * NCOL;
    }
    const int cell_off = bl * BSTR + s2;

    float acc = 0.0f;
    int st = 0;
    uint32_t parity = 0;
    for (int tile = blockIdx.x; tile < NTILES; tile += GRID) {
        mbar_wait(mbar_base + st * 8, parity);

        if (active) {
            const float* base = smem + st * STAGE_F;
            acc += cell_loss(base + cell_off, base + TILE_F + cell_off, row, col);
        }
        __syncthreads();   // all readers done with this stage

        int nxt = tile + NSTAGES * GRID;
        if (tid == 0 && nxt < NTILES)
            issue_tile(smem_base + st * STAGE_B, mbar_base + st * 8, pred, label, nxt);

        if (++st == NSTAGES) { st = 0; parity ^= 1; }
    }

    // ---- Deterministic block reduction ----
    #pragma unroll
    for (int off = 16; off > 0; off >>= 1)
        acc += __shfl_down_sync(0xFFFFFFFFu, acc, off);

    __shared__ float warp_sums[BLOCK / 32];
    if ((tid & 31) == 0) warp_sums[tid >> 5] = acc;
    __syncthreads();

    __shared__ bool is_last;
    if (tid < 32) {
        float v = (tid < BLOCK / 32) ? warp_sums[tid] : 0.0f;
        #pragma unroll
        for (int off = 16; off > 0; off >>= 1)
            v += __shfl_down_sync(0xFFFFFFFFu, v, off);
        if (tid == 0) {
            g_partials[blockIdx.x] = v;
            __threadfence();
            unsigned int ticket = atomicAdd(&g_count, 1u);
            is_last = (ticket == GRID - 1);
        }
    }
    __syncthreads();

    // ---- Final block: deterministic fixed-order sum of partials ----
    if (is_last) {
        float s = 0.0f;
        #pragma unroll
        for (int i = 0; i < (GRID + BLOCK - 1) / BLOCK; i++) {
            int idx = tid + i * BLOCK;
            if (idx < GRID) s += g_partials[idx];
        }
        #pragma unroll
        for (int off = 16; off > 0; off >>= 1)
            s += __shfl_down_sync(0xFFFFFFFFu, s, off);

        __shared__ float fw[BLOCK / 32];
        if ((tid & 31) == 0) fw[tid >> 5] = s;
        __syncthreads();
        if (tid < 32) {
            float v = (tid < BLOCK / 32) ? fw[tid] : 0.0f;
            #pragma unroll
            for (int off = 16; off > 0; off >>= 1)
                v += __shfl_down_sync(0xFFFFFFFFu, v, off);
            if (tid == 0) {
                out[0] = v * (1.0f / (float)BATCH);
                g_count = 0;   // reset for next graph replay
            }
        }
    }
}

extern "C" void kernel_launch(void* const* d_in, const int* in_sizes, int n_in,
                              void* d_out, int out_size) {
    const float* pred  = (const float*)d_in[0];
    const float* label = (const float*)d_in[1];
    float* out = (float*)d_out;

    cudaFuncSetAttribute(yolo_loss_tma,
                         cudaFuncAttributeMaxDynamicSharedMemorySize, SMEM_DYN);
    yolo_loss_tma<<<GRID, BLOCK, SMEM_DYN>>>(pred, label, out);
}